// round 13
// baseline (speedup 1.0000x reference)
#include <cuda_runtime.h>
#include <cuda_bf16.h>
#include <cstring>

// Problem constants
#define B_   64
#define NE_  40000
#define NR_  500
#define D1_  200
#define D2_  200
#define L_   64
#define KSPLIT 200         // one partial per k2
#define LOG2E 1.4426950408889634f
#define NKS   14           // K padded to 224 = 14 k16-steps (score path)
#define KCHUNK 112
#define EPADK 120

typedef unsigned int u32t;

// ---------------- scratch (device globals; no allocation) ----------------
__device__ __align__(16) float g_x0T[D1_ * B_];          // [i][b]
__device__ __align__(16) float g_rT [D2_ * B_];          // [k][b]
__device__ __align__(16) float g_aT [L_ * B_];           // [l][b]
__device__ __align__(16) float g_wT [L_ * B_];           // [l][b]
__device__ __align__(16) float g_negk[L_];               // -sqrt(log2e/var_l)
__device__ __align__(16) float g_ypart[KSPLIT * D1_ * B_];  // 10.2MB
__device__ __align__(16) uint4 g_Afrag[2 * NKS * 4 * 32];

__device__ __forceinline__ float ex2f(float x) {
    float r; asm("ex2.approx.ftz.f32 %0, %1;" : "=f"(r) : "f"(x)); return r;
}
__device__ __forceinline__ float rcpf(float x) {
    float r; asm("rcp.approx.ftz.f32 %0, %1;" : "=f"(r) : "f"(x)); return r;
}
__device__ __forceinline__ u32t pkbf(float x, float y) {
    __nv_bfloat162 h = __floats2bfloat162_rn(x, y);
    u32t r; memcpy(&r, &h, 4); return r;
}
__device__ __forceinline__ void mma16816(float4& c, uint4 a, u32t b0, u32t b1) {
    asm volatile(
        "mma.sync.aligned.m16n8k16.row.col.f32.bf16.bf16.f32 "
        "{%0,%1,%2,%3}, {%4,%5,%6,%7}, {%8,%9}, {%0,%1,%2,%3};"
        : "+f"(c.x), "+f"(c.y), "+f"(c.z), "+f"(c.w)
        : "r"(a.x), "r"(a.y), "r"(a.z), "r"(a.w), "r"(b0), "r"(b1));
}
__device__ __forceinline__ void barnamed(int id) {
    asm volatile("bar.sync %0, 128;" :: "r"(id) : "memory");
}

// ---------------- kernel 1: parallel gather + BN0 + branch prep ----------------
__global__ void k_prep(const int* __restrict__ e1_idx, const int* __restrict__ r_idx,
                       const float* __restrict__ E, const float* __restrict__ R,
                       const float* __restrict__ lits, const float* __restrict__ c,
                       const float* __restrict__ var_l, const float* __restrict__ nf,
                       const float* __restrict__ g0, const float* __restrict__ b0) {
    int blk = blockIdx.x;
    int t = threadIdx.x;
    if (blk < 25) {
        __shared__ int se1[B_];
        if (t < B_) se1[t] = e1_idx[t];
        __syncthreads();
        int j    = blk * 8 + (t >> 5);
        int lane = t & 31;
        float v0 = E[(long)se1[lane] * D1_ + j];
        float v1 = E[(long)se1[lane + 32] * D1_ + j];
        float s = v0 + v1, q = v0 * v0 + v1 * v1;
#pragma unroll
        for (int off = 16; off >= 1; off >>= 1) {
            s += __shfl_xor_sync(0xffffffffu, s, off);
            q += __shfl_xor_sync(0xffffffffu, q, off);
        }
        float mu  = s * (1.f / B_);
        float var = q * (1.f / B_) - mu * mu;
        float sc  = g0[j] * rsqrtf(var + 1e-5f);
        float be  = b0[j];
        g_x0T[j * B_ + lane]      = (v0 - mu) * sc + be;
        g_x0T[j * B_ + 32 + lane] = (v1 - mu) * sc + be;
    } else if (blk < 27) {
        __shared__ int sr[B_];
        if (t < B_) sr[t] = r_idx[t];
        __syncthreads();
        int base = (blk - 25) * (D2_ * B_ / 2);
        for (int idx = t; idx < D2_ * B_ / 2; idx += 256) {
            int k = (base + idx) >> 6, b = (base + idx) & 63;
            g_rT[base + idx] = R[(long)sr[b] * D2_ + k];
        }
    } else {
        __shared__ int se1[B_], sr[B_];
        if (t < B_) { se1[t] = e1_idx[t]; sr[t] = r_idx[t]; }
        __syncthreads();
        if (t < L_) g_negk[t] = -sqrtf(LOG2E / var_l[t]);
        for (int idx = t; idx < B_ * L_; idx += 256) {
            int b = idx & 63, l = idx >> 6;
            float ks = sqrtf(LOG2E / var_l[l]);
            g_aT[l * B_ + b] = (lits[(long)se1[b] * L_ + l] - c[l]) * ks;
            g_wT[l * B_ + b] = nf[(long)sr[b] * L_ + l];
        }
    }
}

// ---------------- kernel 2: W contraction via bf16 hi/lo mma ----------------
// grid 200 (one per k2), block 256 = 8 warps: mt = warp&3 (16 b), nh = warp>>2.
// A: z[b][i] = rT[k2][b]*x0T[i][b] (built in regs), B: W[k2][i][j] staged hi/lo.
// C partials -> g_ypart[k2][j][b].
#define WROW 24    // bf16 row stride (48B) for conflict-free B-frag LDS
__global__ __launch_bounds__(256) void k_wgemm(const float* __restrict__ W) {
    __shared__ __align__(16) char sbuf[D1_ * 68 * 4];    // 54.4KB: W stage OR out tile
    __nv_bfloat16* Wbh = (__nv_bfloat16*)sbuf;           // [j*WROW + il]
    __nv_bfloat16* Wbl = (__nv_bfloat16*)(sbuf + D1_ * WROW * 2);
    float* sOut = (float*)sbuf;                          // [j*68 + b]

    int k2   = blockIdx.x;
    int t    = threadIdx.x;
    int lane = t & 31;
    int warp = t >> 5;
    int mt   = warp & 3;
    int nh   = warp >> 2;
    int ntiles = nh ? 12 : 13;
    int jbase  = nh * 104;
    int r0   = mt * 16 + (lane >> 2);

    float rv0 = g_rT[k2 * B_ + r0];
    float rv1 = g_rT[k2 * B_ + r0 + 8];
    const float* Wk = W + (long)k2 * (D1_ * D1_);

    float4 acc[13];
#pragma unroll
    for (int u = 0; u < 13; u++) acc[u] = make_float4(0.f, 0.f, 0.f, 0.f);

#pragma unroll 1
    for (int st = 0; st < 13; st++) {
        int i0 = st * 16;
        __syncthreads();
        // stage W rows i0..i0+15 (x 200 j) as bf16 hi/lo, transposed to [j][il]
        for (int q = t; q < 16 * 50; q += 256) {
            int il = q / 50, j4 = (q % 50) * 4;
            int i  = i0 + il;
            float4 w = (i < D1_) ? *(const float4*)&Wk[i * D1_ + j4]
                                 : make_float4(0.f, 0.f, 0.f, 0.f);
            float vs[4] = {w.x, w.y, w.z, w.w};
#pragma unroll
            for (int s = 0; s < 4; s++) {
                __nv_bfloat16 h = __float2bfloat16_rn(vs[s]);
                Wbh[(j4 + s) * WROW + il] = h;
                Wbl[(j4 + s) * WROW + il] = __float2bfloat16_rn(vs[s] - __bfloat162float(h));
            }
        }
        __syncthreads();
        // build A-fragment for this k16 step (z = rv * x0, hi/lo split)
        int c0 = i0 + 2 * (lane & 3);
        float zh[2][4], zl[2][4];
#pragma unroll
        for (int rr = 0; rr < 2; rr++) {
            int r = r0 + rr * 8;
            float rv = rr ? rv1 : rv0;
#pragma unroll
            for (int cc = 0; cc < 4; cc++) {
                int ci = c0 + (cc & 1) + (cc >> 1) * 8;
                float x = (ci < D1_) ? g_x0T[ci * B_ + r] : 0.f;
                float z = rv * x;
                float h = __bfloat162float(__float2bfloat16_rn(z));
                zh[rr][cc] = h;
                zl[rr][cc] = z - h;
            }
        }
        uint4 AH, AL;
        AH.x = pkbf(zh[0][0], zh[0][1]); AH.y = pkbf(zh[1][0], zh[1][1]);
        AH.z = pkbf(zh[0][2], zh[0][3]); AH.w = pkbf(zh[1][2], zh[1][3]);
        AL.x = pkbf(zl[0][0], zl[0][1]); AL.y = pkbf(zl[1][0], zl[1][1]);
        AL.z = pkbf(zl[0][2], zl[0][3]); AL.w = pkbf(zl[1][2], zl[1][3]);

        int kb = 2 * (lane & 3);
#pragma unroll
        for (int tile = 0; tile < 13; tile++) {
            if (tile >= ntiles) break;
            int n = jbase + tile * 8 + (lane >> 2);
            u32t bh0 = *(const u32t*)&Wbh[n * WROW + kb];
            u32t bh1 = *(const u32t*)&Wbh[n * WROW + kb + 8];
            u32t bl0 = *(const u32t*)&Wbl[n * WROW + kb];
            u32t bl1 = *(const u32t*)&Wbl[n * WROW + kb + 8];
            mma16816(acc[tile], AH, bh0, bh1);
            mma16816(acc[tile], AH, bl0, bl1);
            mma16816(acc[tile], AL, bh0, bh1);
        }
    }
    __syncthreads();
    // write accs to sOut[j][b] (padded 68), then coalesced STG to ypart
    {
        int cc0 = 2 * (lane & 3);
#pragma unroll
        for (int tile = 0; tile < 13; tile++) {
            if (tile >= ntiles) break;
            int cj = jbase + tile * 8 + cc0;
            sOut[cj * 68 + r0]           = acc[tile].x;
            sOut[(cj + 1) * 68 + r0]     = acc[tile].y;
            sOut[cj * 68 + r0 + 8]       = acc[tile].z;
            sOut[(cj + 1) * 68 + r0 + 8] = acc[tile].w;
        }
    }
    __syncthreads();
    float* yp = g_ypart + (long)k2 * (D1_ * B_);
    for (int q = t; q < D1_ * 16; q += 256) {
        int j = q >> 4, b4 = (q & 15) * 4;
        *(float4*)&yp[j * B_ + b4] = *(const float4*)&sOut[j * 68 + b4];
    }
}

// ---------------- kernel 3: reduce + BN1 + A-fragment build (fused) ----------------
__global__ __launch_bounds__(512) void k_bn1f(const float* __restrict__ g1,
                                              const float* __restrict__ b1) {
    __shared__ float x1s[16][64];
    int t    = threadIdx.x;
    int wid  = t >> 5;
    int lane = t & 31;
    int blk  = blockIdx.x;
    int j    = blk * 16 + wid;

    if (j < D1_) {
        float y0 = 0.f, y1 = 0.f;
#pragma unroll 8
        for (int ks = 0; ks < KSPLIT; ks++) {
            y0 += g_ypart[ks * (D1_ * B_) + j * B_ + lane];
            y1 += g_ypart[ks * (D1_ * B_) + j * B_ + 32 + lane];
        }
        float s = y0 + y1, q = y0 * y0 + y1 * y1;
#pragma unroll
        for (int off = 16; off >= 1; off >>= 1) {
            s += __shfl_xor_sync(0xffffffffu, s, off);
            q += __shfl_xor_sync(0xffffffffu, q, off);
        }
        float mu  = s * (1.f / B_);
        float var = q * (1.f / B_) - mu * mu;
        float sc  = g1[j] * rsqrtf(var + 1e-5f);
        float be  = b1[j];
        x1s[wid][lane]      = (y0 - mu) * sc + be;
        x1s[wid][lane + 32] = (y1 - mu) * sc + be;
    } else {
        x1s[wid][lane] = 0.f;
        x1s[wid][lane + 32] = 0.f;
    }
    __syncthreads();

    if (wid < 4) {
        int mt = wid;
        int r0 = mt * 16 + (lane >> 2);
        int c0 = 2 * (lane & 3);
        float vh[2][4], vl[2][4];
#pragma unroll
        for (int rr = 0; rr < 2; rr++) {
            int r = r0 + rr * 8;
#pragma unroll
            for (int cc = 0; cc < 4; cc++) {
                int cl = c0 + (cc & 1) + (cc >> 1) * 8;
                float x = x1s[cl][r];
                float h = __bfloat162float(__float2bfloat16_rn(x));
                vh[rr][cc] = h;
                vl[rr][cc] = x - h;
            }
        }
        uint4 H, L;
        H.x = pkbf(vh[0][0], vh[0][1]); H.y = pkbf(vh[1][0], vh[1][1]);
        H.z = pkbf(vh[0][2], vh[0][3]); H.w = pkbf(vh[1][2], vh[1][3]);
        L.x = pkbf(vl[0][0], vl[0][1]); L.y = pkbf(vl[1][0], vl[1][1]);
        L.z = pkbf(vl[0][2], vl[0][3]); L.w = pkbf(vl[1][2], vl[1][3]);
        int base = (blk * 4 + mt) * 32 + lane;
        g_Afrag[base]                = H;
        g_Afrag[base + NKS * 4 * 32] = L;
    }
}

// ---------------- kernel 4: warp-specialized score (tensor mma || MUFU KBLN) ----------------
__global__ __launch_bounds__(256) void k_score(
    const float* __restrict__ E, const float* __restrict__ lits,
    const float* __restrict__ var_l, float* __restrict__ out) {

    __shared__ __align__(16) char u_buf[2 * 64 * EPADK * 2];
    __shared__ __align__(16) float Ssn[64][68];

    __nv_bfloat16* eb = (__nv_bfloat16*)u_buf;
    float (*scores)[76] = (float (*)[76])u_buf;

    int t    = threadIdx.x;
    int lane = t & 31;
    int warp = t >> 5;
    int n0   = blockIdx.x * 64;

    if (warp < 4) {
        // ---- mma group: threads 0..127 ----
        int mt = warp;
        float4 acc[8];
#pragma unroll
        for (int u = 0; u < 8; u++) acc[u] = make_float4(0.f, 0.f, 0.f, 0.f);

#pragma unroll 1
        for (int chunk = 0; chunk < 2; chunk++) {
            int kb = chunk * KCHUNK;
            for (int idx = t; idx < 64 * (KCHUNK / 4); idx += 128) {
                int row = idx / (KCHUNK / 4);
                int kq  = (idx % (KCHUNK / 4)) * 4;
                int kg  = kb + kq;
                float v0, v1, v2, v3;
                if (kg + 3 < D1_) {
                    float4 v = *(const float4*)&E[(long)(n0 + row) * D1_ + kg];
                    v0 = v.x; v1 = v.y; v2 = v.z; v3 = v.w;
                } else {
                    v0 = (kg     < D1_) ? E[(long)(n0 + row) * D1_ + kg]     : 0.f;
                    v1 = (kg + 1 < D1_) ? E[(long)(n0 + row) * D1_ + kg + 1] : 0.f;
                    v2 = (kg + 2 < D1_) ? E[(long)(n0 + row) * D1_ + kg + 2] : 0.f;
                    v3 = (kg + 3 < D1_) ? E[(long)(n0 + row) * D1_ + kg + 3] : 0.f;
                }
                float h0 = __bfloat162float(__float2bfloat16_rn(v0));
                float h1 = __bfloat162float(__float2bfloat16_rn(v1));
                float h2 = __bfloat162float(__float2bfloat16_rn(v2));
                float h3 = __bfloat162float(__float2bfloat16_rn(v3));
                *(u32t*)&eb[row * EPADK + kq]            = pkbf(h0, h1);
                *(u32t*)&eb[row * EPADK + kq + 2]        = pkbf(h2, h3);
                *(u32t*)&eb[(64 + row) * EPADK + kq]     = pkbf(v0 - h0, v1 - h1);
                *(u32t*)&eb[(64 + row) * EPADK + kq + 2] = pkbf(v2 - h2, v3 - h3);
            }
            barnamed(1);
            int kslim = chunk ? 6 : 7;
#pragma unroll 1
            for (int ksl = 0; ksl < kslim; ksl++) {
                int ks = chunk * 7 + ksl;
                uint4 AH = g_Afrag[(ks * 4 + mt) * 32 + lane];
                uint4 AL = g_Afrag[(ks * 4 + mt) * 32 + lane + NKS * 4 * 32];
                int kloc = ksl * 16 + 2 * (lane & 3);
#pragma unroll
                for (int tile = 0; tile < 8; tile++) {
                    int n = tile * 8 + (lane >> 2);
                    u32t bh0 = *(const u32t*)&eb[n * EPADK + kloc];
                    u32t bh1 = *(const u32t*)&eb[n * EPADK + kloc + 8];
                    u32t bl0 = *(const u32t*)&eb[(64 + n) * EPADK + kloc];
                    u32t bl1 = *(const u32t*)&eb[(64 + n) * EPADK + kloc + 8];
                    mma16816(acc[tile], AH, bh0, bh1);
                    mma16816(acc[tile], AH, bl0, bl1);
                    mma16816(acc[tile], AL, bh0, bh1);
                }
            }
            barnamed(1);
        }
        {
            int sr = mt * 16 + (lane >> 2);
            int sc = 2 * (lane & 3);
#pragma unroll
            for (int tile = 0; tile < 8; tile++) {
                *(float2*)&scores[sr][sc + tile * 8]     = make_float2(acc[tile].x, acc[tile].y);
                *(float2*)&scores[sr + 8][sc + tile * 8] = make_float2(acc[tile].z, acc[tile].w);
            }
        }
        __syncthreads();
    } else {
        // ---- KBLN group: threads 128..255 ----
        int tl = t - 128;
        for (int i = tl; i < 64 * 64; i += 128) {
            int l = i & 63, nl = i >> 6;
            Ssn[l][nl] = lits[(long)(n0 + nl) * L_ + l] * g_negk[l];
        }
        barnamed(2);

        int nbase = (warp - 4) * 16;
        float acc0[16], acc1[16];
#pragma unroll
        for (int u = 0; u < 16; u++) { acc0[u] = 0.f; acc1[u] = 0.f; }

        const float2* aT2 = (const float2*)g_aT;
        const float2* wT2 = (const float2*)g_wT;
#pragma unroll 1
        for (int lc = 0; lc < 16; lc++) {
            int l0 = lc * 4;
            float2 a2[4], w2[4];
#pragma unroll
            for (int u = 0; u < 4; u++) {
                a2[u] = aT2[(l0 + u) * 32 + lane];
                w2[u] = wT2[(l0 + u) * 32 + lane];
            }
#pragma unroll
            for (int u = 0; u < 4; u++) {
                float4 svA = *(const float4*)&Ssn[l0 + u][nbase];
                float4 svB = *(const float4*)&Ssn[l0 + u][nbase + 4];
                float4 svC = *(const float4*)&Ssn[l0 + u][nbase + 8];
                float4 svD = *(const float4*)&Ssn[l0 + u][nbase + 12];
                float sv[16] = {svA.x, svA.y, svA.z, svA.w, svB.x, svB.y, svB.z, svB.w,
                                svC.x, svC.y, svC.z, svC.w, svD.x, svD.y, svD.z, svD.w};
#pragma unroll
                for (int nn = 0; nn < 16; nn++) {
                    float d0 = a2[u].x + sv[nn];
                    float d1 = a2[u].y + sv[nn];
                    acc0[nn] += w2[u].x * ex2f(-d0 * d0);
                    acc1[nn] += w2[u].y * ex2f(-d1 * d1);
                }
            }
        }
        __syncthreads();

        int b0r = 2 * lane, b1r = b0r + 1;
#pragma unroll
        for (int g = 0; g < 4; g++) {
            float4 s0 = *(const float4*)&scores[b0r][nbase + g * 4];
            float4 s1 = *(const float4*)&scores[b1r][nbase + g * 4];
            float o0x = rcpf(1.f + ex2f(-LOG2E * (s0.x + acc0[g * 4 + 0])));
            float o0y = rcpf(1.f + ex2f(-LOG2E * (s0.y + acc0[g * 4 + 1])));
            float o0z = rcpf(1.f + ex2f(-LOG2E * (s0.z + acc0[g * 4 + 2])));
            float o0w = rcpf(1.f + ex2f(-LOG2E * (s0.w + acc0[g * 4 + 3])));
            float o1x = rcpf(1.f + ex2f(-LOG2E * (s1.x + acc1[g * 4 + 0])));
            float o1y = rcpf(1.f + ex2f(-LOG2E * (s1.y + acc1[g * 4 + 1])));
            float o1z = rcpf(1.f + ex2f(-LOG2E * (s1.z + acc1[g * 4 + 2])));
            float o1w = rcpf(1.f + ex2f(-LOG2E * (s1.w + acc1[g * 4 + 3])));
            int n = n0 + nbase + g * 4;
            *(float4*)&out[(long)b0r * NE_ + n] = make_float4(o0x, o0y, o0z, o0w);
            *(float4*)&out[(long)b1r * NE_ + n] = make_float4(o1x, o1y, o1z, o1w);
        }
    }
}

// ---------------- launch ----------------
extern "C" void kernel_launch(void* const* d_in, const int* in_sizes, int n_in,
                              void* d_out, int out_size) {
    const int*   e1_idx = (const int*)  d_in[0];
    const int*   r_idx  = (const int*)  d_in[1];
    const float* E      = (const float*)d_in[2];
    const float* R      = (const float*)d_in[3];
    const float* W      = (const float*)d_in[4];
    const float* lits   = (const float*)d_in[5];
    const float* c      = (const float*)d_in[6];
    const float* var_l  = (const float*)d_in[7];
    const float* nf     = (const float*)d_in[8];
    const float* g0     = (const float*)d_in[9];
    const float* b0     = (const float*)d_in[10];
    const float* g1     = (const float*)d_in[11];
    const float* b1     = (const float*)d_in[12];
    float* out = (float*)d_out;

    k_prep<<<28, 256>>>(e1_idx, r_idx, E, R, lits, c, var_l, nf, g0, b0);
    k_wgemm<<<KSPLIT, 256>>>(W);
    k_bn1f<<<13, 512>>>(g1, b1);
    k_score<<<NE_ / 64, 256>>>(E, lits, var_l, out);
}

// round 14
// speedup vs baseline: 1.1763x; 1.1763x over previous
#include <cuda_runtime.h>
#include <cuda_bf16.h>
#include <cstring>

// Problem constants
#define B_   64
#define NE_  40000
#define NR_  500
#define D1_  200
#define D2_  200
#define L_   64
#define KSPLIT 200         // one partial per k2
#define LOG2E 1.4426950408889634f
#define NKS   14           // score path: K padded to 224
#define KCHUNK 112
#define EPADK 120
#define WSTRIDE 216        // wgemm B stage: bf16 per row (432B, 16B-aligned, conflict-free)
#define WPLANE  (16 * WSTRIDE)          // bf16 units per plane (hi or lo)
#define WBUFB   (2 * WPLANE * 2)        // bytes per buffer (hi+lo) = 13824

typedef unsigned int u32t;

// ---------------- scratch (device globals; no allocation) ----------------
__device__ __align__(16) float g_x0T[D1_ * B_];          // [i][b]
__device__ __align__(16) float g_rT [D2_ * B_];          // [k][b]
__device__ __align__(16) float g_aT [L_ * B_];           // [l][b]
__device__ __align__(16) float g_wT [L_ * B_];           // [l][b]
__device__ __align__(16) float g_negk[L_];               // -sqrt(log2e/var_l)
__device__ __align__(16) float g_ypart[KSPLIT * D1_ * B_];
__device__ __align__(16) uint4 g_Afrag[2 * NKS * 4 * 32];

__device__ __forceinline__ float ex2f(float x) {
    float r; asm("ex2.approx.ftz.f32 %0, %1;" : "=f"(r) : "f"(x)); return r;
}
__device__ __forceinline__ float rcpf(float x) {
    float r; asm("rcp.approx.ftz.f32 %0, %1;" : "=f"(r) : "f"(x)); return r;
}
__device__ __forceinline__ u32t pkbf(float x, float y) {
    __nv_bfloat162 h = __floats2bfloat162_rn(x, y);
    u32t r; memcpy(&r, &h, 4); return r;
}
__device__ __forceinline__ void mma16816(float4& c, uint4 a, u32t b0, u32t b1) {
    asm volatile(
        "mma.sync.aligned.m16n8k16.row.col.f32.bf16.bf16.f32 "
        "{%0,%1,%2,%3}, {%4,%5,%6,%7}, {%8,%9}, {%0,%1,%2,%3};"
        : "+f"(c.x), "+f"(c.y), "+f"(c.z), "+f"(c.w)
        : "r"(a.x), "r"(a.y), "r"(a.z), "r"(a.w), "r"(b0), "r"(b1));
}
__device__ __forceinline__ void ldmx2t(u32t& r0, u32t& r1, u32t addr) {
    asm volatile("ldmatrix.sync.aligned.m8n8.x2.trans.shared.b16 {%0,%1}, [%2];"
                 : "=r"(r0), "=r"(r1) : "r"(addr));
}
__device__ __forceinline__ void barnamed(int id, int cnt) {
    asm volatile("bar.sync %0, %1;" :: "r"(id), "r"(cnt) : "memory");
}
__device__ __forceinline__ u32t smem_u32(const void* p) {
    u32t a; asm("{ .reg .u64 t; cvta.to.shared.u64 t, %1; cvt.u32.u64 %0, t; }"
                : "=r"(a) : "l"(p));
    return a;
}

// ---------------- kernel 1: parallel gather + BN0 + branch prep ----------------
__global__ void k_prep(const int* __restrict__ e1_idx, const int* __restrict__ r_idx,
                       const float* __restrict__ E, const float* __restrict__ R,
                       const float* __restrict__ lits, const float* __restrict__ c,
                       const float* __restrict__ var_l, const float* __restrict__ nf,
                       const float* __restrict__ g0, const float* __restrict__ b0) {
    int blk = blockIdx.x;
    int t = threadIdx.x;
    if (blk < 25) {
        __shared__ int se1[B_];
        if (t < B_) se1[t] = e1_idx[t];
        __syncthreads();
        int j    = blk * 8 + (t >> 5);
        int lane = t & 31;
        float v0 = E[(long)se1[lane] * D1_ + j];
        float v1 = E[(long)se1[lane + 32] * D1_ + j];
        float s = v0 + v1, q = v0 * v0 + v1 * v1;
#pragma unroll
        for (int off = 16; off >= 1; off >>= 1) {
            s += __shfl_xor_sync(0xffffffffu, s, off);
            q += __shfl_xor_sync(0xffffffffu, q, off);
        }
        float mu  = s * (1.f / B_);
        float var = q * (1.f / B_) - mu * mu;
        float sc  = g0[j] * rsqrtf(var + 1e-5f);
        float be  = b0[j];
        g_x0T[j * B_ + lane]      = (v0 - mu) * sc + be;
        g_x0T[j * B_ + 32 + lane] = (v1 - mu) * sc + be;
    } else if (blk < 27) {
        __shared__ int sr[B_];
        if (t < B_) sr[t] = r_idx[t];
        __syncthreads();
        int base = (blk - 25) * (D2_ * B_ / 2);
        for (int idx = t; idx < D2_ * B_ / 2; idx += 256) {
            int k = (base + idx) >> 6, b = (base + idx) & 63;
            g_rT[base + idx] = R[(long)sr[b] * D2_ + k];
        }
    } else {
        __shared__ int se1[B_], sr[B_];
        if (t < B_) { se1[t] = e1_idx[t]; sr[t] = r_idx[t]; }
        __syncthreads();
        if (t < L_) g_negk[t] = -sqrtf(LOG2E / var_l[t]);
        for (int idx = t; idx < B_ * L_; idx += 256) {
            int b = idx & 63, l = idx >> 6;
            float ks = sqrtf(LOG2E / var_l[l]);
            g_aT[l * B_ + b] = (lits[(long)se1[b] * L_ + l] - c[l]) * ks;
            g_wT[l * B_ + b] = nf[(long)sr[b] * L_ + l];
        }
    }
}

// ---------------- kernel 2: W contraction via mma + ldmatrix.trans ----------------
// grid 200 (one per k2), block 256 = 8 warps: mt = warp&3 (16 b-rows), nh = warp>>2.
// B staged j-contiguous bf16 hi/lo (no transpose); LDSM.trans makes B-fragments.
__global__ __launch_bounds__(256) void k_wgemm(const float* __restrict__ W) {
    __shared__ __align__(16) char sbuf[D1_ * 68 * 4];    // max(2*13824, 54400)
    float* sOut = (float*)sbuf;

    int k2   = blockIdx.x;
    int t    = threadIdx.x;
    int lane = t & 31;
    int warp = t >> 5;
    int mt   = warp & 3;
    int nh   = warp >> 2;
    int ntiles = nh ? 12 : 13;
    int jbase  = nh * 104;
    int r0   = mt * 16 + (lane >> 2);

    float rv0 = g_rT[k2 * B_ + r0];
    float rv1 = g_rT[k2 * B_ + r0 + 8];
    const float* Wk = W + (long)k2 * (D1_ * D1_);
    u32t sb32 = smem_u32(sbuf);
    u32t rowoff = (lane & 15) * (WSTRIDE * 2);   // byte offset of this lane's k-row

    float4 acc[13];
#pragma unroll
    for (int u = 0; u < 13; u++) acc[u] = make_float4(0.f, 0.f, 0.f, 0.f);

    // stage W rows i0..i0+15 (x 200 j) as bf16 hi/lo, j-contiguous, into buffer p
    #define WSTAGE(st, p) {                                                   \
        int i0_ = (st) * 16;                                                  \
        __nv_bfloat16* bh = (__nv_bfloat16*)(sbuf + (p) * WBUFB);             \
        __nv_bfloat16* bl = bh + WPLANE;                                      \
        for (int q = t; q < 16 * 50; q += 256) {                              \
            int il = q / 50, j4 = (q % 50) * 4;                               \
            int i  = i0_ + il;                                                \
            float4 w = (i < D1_) ? *(const float4*)&Wk[i * D1_ + j4]          \
                                 : make_float4(0.f, 0.f, 0.f, 0.f);           \
            float h0 = __bfloat162float(__float2bfloat16_rn(w.x));            \
            float h1 = __bfloat162float(__float2bfloat16_rn(w.y));            \
            float h2 = __bfloat162float(__float2bfloat16_rn(w.z));            \
            float h3 = __bfloat162float(__float2bfloat16_rn(w.w));            \
            *(u32t*)&bh[il * WSTRIDE + j4]     = pkbf(h0, h1);                \
            *(u32t*)&bh[il * WSTRIDE + j4 + 2] = pkbf(h2, h3);                \
            *(u32t*)&bl[il * WSTRIDE + j4]     = pkbf(w.x - h0, w.y - h1);    \
            *(u32t*)&bl[il * WSTRIDE + j4 + 2] = pkbf(w.z - h2, w.w - h3);    \
        }                                                                     \
    }

    WSTAGE(0, 0);
#pragma unroll 1
    for (int st = 0; st < 13; st++) {
        __syncthreads();
        if (st < 12) WSTAGE(st + 1, (st + 1) & 1);
        int p  = st & 1;
        int i0 = st * 16;
        // A-fragment: z = rv * x0, bf16 hi/lo (identical to validated R13 path)
        int c0 = i0 + 2 * (lane & 3);
        float zh[2][4], zl[2][4];
#pragma unroll
        for (int rr = 0; rr < 2; rr++) {
            int r = r0 + rr * 8;
            float rv = rr ? rv1 : rv0;
#pragma unroll
            for (int cc = 0; cc < 4; cc++) {
                int ci = c0 + (cc & 1) + (cc >> 1) * 8;
                float x = (ci < D1_) ? g_x0T[ci * B_ + r] : 0.f;
                float z = rv * x;
                float h = __bfloat162float(__float2bfloat16_rn(z));
                zh[rr][cc] = h;
                zl[rr][cc] = z - h;
            }
        }
        uint4 AH, AL;
        AH.x = pkbf(zh[0][0], zh[0][1]); AH.y = pkbf(zh[1][0], zh[1][1]);
        AH.z = pkbf(zh[0][2], zh[0][3]); AH.w = pkbf(zh[1][2], zh[1][3]);
        AL.x = pkbf(zl[0][0], zl[0][1]); AL.y = pkbf(zl[1][0], zl[1][1]);
        AL.z = pkbf(zl[0][2], zl[0][3]); AL.w = pkbf(zl[1][2], zl[1][3]);

        u32t hibase = sb32 + p * WBUFB + rowoff;
#pragma unroll
        for (int tile = 0; tile < 13; tile++) {
            if (tile >= ntiles) break;
            int n0 = jbase + tile * 8;
            u32t bh0, bh1, bl0, bl1;
            ldmx2t(bh0, bh1, hibase + n0 * 2);
            ldmx2t(bl0, bl1, hibase + WPLANE * 2 + n0 * 2);
            mma16816(acc[tile], AH, bh0, bh1);
            mma16816(acc[tile], AH, bl0, bl1);
            mma16816(acc[tile], AL, bh0, bh1);
        }
    }
    #undef WSTAGE

    __syncthreads();
    {
        int cc0 = 2 * (lane & 3);
#pragma unroll
        for (int tile = 0; tile < 13; tile++) {
            if (tile >= ntiles) break;
            int cj = jbase + tile * 8 + cc0;
            sOut[cj * 68 + r0]           = acc[tile].x;
            sOut[(cj + 1) * 68 + r0]     = acc[tile].y;
            sOut[cj * 68 + r0 + 8]       = acc[tile].z;
            sOut[(cj + 1) * 68 + r0 + 8] = acc[tile].w;
        }
    }
    __syncthreads();
    float* yp = g_ypart + (long)k2 * (D1_ * B_);
    for (int q = t; q < D1_ * 16; q += 256) {
        int j = q >> 4, b4 = (q & 15) * 4;
        *(float4*)&yp[j * B_ + b4] = *(const float4*)&sOut[j * 68 + b4];
    }
}

// ---------------- kernel 3: reduce + BN1 + A-fragment build (fused) ----------------
__global__ __launch_bounds__(512) void k_bn1f(const float* __restrict__ g1,
                                              const float* __restrict__ b1) {
    __shared__ float x1s[16][64];
    int t    = threadIdx.x;
    int wid  = t >> 5;
    int lane = t & 31;
    int blk  = blockIdx.x;
    int j    = blk * 16 + wid;

    if (j < D1_) {
        float y0 = 0.f, y1 = 0.f;
#pragma unroll 8
        for (int ks = 0; ks < KSPLIT; ks++) {
            y0 += g_ypart[ks * (D1_ * B_) + j * B_ + lane];
            y1 += g_ypart[ks * (D1_ * B_) + j * B_ + 32 + lane];
        }
        float s = y0 + y1, q = y0 * y0 + y1 * y1;
#pragma unroll
        for (int off = 16; off >= 1; off >>= 1) {
            s += __shfl_xor_sync(0xffffffffu, s, off);
            q += __shfl_xor_sync(0xffffffffu, q, off);
        }
        float mu  = s * (1.f / B_);
        float var = q * (1.f / B_) - mu * mu;
        float sc  = g1[j] * rsqrtf(var + 1e-5f);
        float be  = b1[j];
        x1s[wid][lane]      = (y0 - mu) * sc + be;
        x1s[wid][lane + 32] = (y1 - mu) * sc + be;
    } else {
        x1s[wid][lane] = 0.f;
        x1s[wid][lane + 32] = 0.f;
    }
    __syncthreads();

    if (wid < 4) {
        int mt = wid;
        int r0 = mt * 16 + (lane >> 2);
        int c0 = 2 * (lane & 3);
        float vh[2][4], vl[2][4];
#pragma unroll
        for (int rr = 0; rr < 2; rr++) {
            int r = r0 + rr * 8;
#pragma unroll
            for (int cc = 0; cc < 4; cc++) {
                int cl = c0 + (cc & 1) + (cc >> 1) * 8;
                float x = x1s[cl][r];
                float h = __bfloat162float(__float2bfloat16_rn(x));
                vh[rr][cc] = h;
                vl[rr][cc] = x - h;
            }
        }
        uint4 H, L;
        H.x = pkbf(vh[0][0], vh[0][1]); H.y = pkbf(vh[1][0], vh[1][1]);
        H.z = pkbf(vh[0][2], vh[0][3]); H.w = pkbf(vh[1][2], vh[1][3]);
        L.x = pkbf(vl[0][0], vl[0][1]); L.y = pkbf(vl[1][0], vl[1][1]);
        L.z = pkbf(vl[0][2], vl[0][3]); L.w = pkbf(vl[1][2], vl[1][3]);
        int base = (blk * 4 + mt) * 32 + lane;
        g_Afrag[base]                = H;
        g_Afrag[base + NKS * 4 * 32] = L;
    }
}

// ---------------- kernel 4: warp-specialized score ----------------
// grid 625, block 384: warps 0-3 = mma group (score_l), warps 4-11 = KBLN (2/SMSP).
__global__ __launch_bounds__(384) void k_score(
    const float* __restrict__ E, const float* __restrict__ lits,
    float* __restrict__ out) {

    __shared__ __align__(16) char u_buf[2 * 64 * EPADK * 2];
    __shared__ __align__(16) float Ssn[64][68];

    __nv_bfloat16* eb = (__nv_bfloat16*)u_buf;
    float (*scores)[76] = (float (*)[76])u_buf;

    int t    = threadIdx.x;
    int lane = t & 31;
    int warp = t >> 5;
    int n0   = blockIdx.x * 64;

    if (warp < 4) {
        // ---- mma group: threads 0..127 ----
        int mt = warp;
        float4 acc[8];
#pragma unroll
        for (int u = 0; u < 8; u++) acc[u] = make_float4(0.f, 0.f, 0.f, 0.f);

#pragma unroll 1
        for (int chunk = 0; chunk < 2; chunk++) {
            int kb = chunk * KCHUNK;
            for (int idx = t; idx < 64 * (KCHUNK / 4); idx += 128) {
                int row = idx / (KCHUNK / 4);
                int kq  = (idx % (KCHUNK / 4)) * 4;
                int kg  = kb + kq;
                float v0, v1, v2, v3;
                if (kg + 3 < D1_) {
                    float4 v = *(const float4*)&E[(long)(n0 + row) * D1_ + kg];
                    v0 = v.x; v1 = v.y; v2 = v.z; v3 = v.w;
                } else {
                    v0 = (kg     < D1_) ? E[(long)(n0 + row) * D1_ + kg]     : 0.f;
                    v1 = (kg + 1 < D1_) ? E[(long)(n0 + row) * D1_ + kg + 1] : 0.f;
                    v2 = (kg + 2 < D1_) ? E[(long)(n0 + row) * D1_ + kg + 2] : 0.f;
                    v3 = (kg + 3 < D1_) ? E[(long)(n0 + row) * D1_ + kg + 3] : 0.f;
                }
                float h0 = __bfloat162float(__float2bfloat16_rn(v0));
                float h1 = __bfloat162float(__float2bfloat16_rn(v1));
                float h2 = __bfloat162float(__float2bfloat16_rn(v2));
                float h3 = __bfloat162float(__float2bfloat16_rn(v3));
                *(u32t*)&eb[row * EPADK + kq]            = pkbf(h0, h1);
                *(u32t*)&eb[row * EPADK + kq + 2]        = pkbf(h2, h3);
                *(u32t*)&eb[(64 + row) * EPADK + kq]     = pkbf(v0 - h0, v1 - h1);
                *(u32t*)&eb[(64 + row) * EPADK + kq + 2] = pkbf(v2 - h2, v3 - h3);
            }
            barnamed(1, 128);
            int kslim = chunk ? 6 : 7;
#pragma unroll 1
            for (int ksl = 0; ksl < kslim; ksl++) {
                int ks = chunk * 7 + ksl;
                uint4 AH = g_Afrag[(ks * 4 + mt) * 32 + lane];
                uint4 AL = g_Afrag[(ks * 4 + mt) * 32 + lane + NKS * 4 * 32];
                int kloc = ksl * 16 + 2 * (lane & 3);
#pragma unroll
                for (int tile = 0; tile < 8; tile++) {
                    int n = tile * 8 + (lane >> 2);
                    u32t bh0 = *(const u32t*)&eb[n * EPADK + kloc];
                    u32t bh1 = *(const u32t*)&eb[n * EPADK + kloc + 8];
                    u32t bl0 = *(const u32t*)&eb[(64 + n) * EPADK + kloc];
                    u32t bl1 = *(const u32t*)&eb[(64 + n) * EPADK + kloc + 8];
                    mma16816(acc[tile], AH, bh0, bh1);
                    mma16816(acc[tile], AH, bl0, bl1);
                    mma16816(acc[tile], AL, bh0, bh1);
                }
            }
            barnamed(1, 128);
        }
        {
            int sr = mt * 16 + (lane >> 2);
            int sc = 2 * (lane & 3);
#pragma unroll
            for (int tile = 0; tile < 8; tile++) {
                *(float2*)&scores[sr][sc + tile * 8]     = make_float2(acc[tile].x, acc[tile].y);
                *(float2*)&scores[sr + 8][sc + tile * 8] = make_float2(acc[tile].z, acc[tile].w);
            }
        }
        __syncthreads();
    } else {
        // ---- KBLN group: threads 128..383 (8 warps, 8 n each) ----
        int tl = t - 128;
        for (int i = tl; i < 64 * 64; i += 256) {
            int l = i & 63, nl = i >> 6;
            Ssn[l][nl] = lits[(long)(n0 + nl) * L_ + l] * g_negk[l];
        }
        barnamed(2, 256);

        int nbase = (warp - 4) * 8;
        float acc0[8], acc1[8];
#pragma unroll
        for (int u = 0; u < 8; u++) { acc0[u] = 0.f; acc1[u] = 0.f; }

        const float2* aT2 = (const float2*)g_aT;
        const float2* wT2 = (const float2*)g_wT;
#pragma unroll 1
        for (int lc = 0; lc < 16; lc++) {
            int l0 = lc * 4;
            float2 a2[4], w2[4];
#pragma unroll
            for (int u = 0; u < 4; u++) {
                a2[u] = aT2[(l0 + u) * 32 + lane];
                w2[u] = wT2[(l0 + u) * 32 + lane];
            }
#pragma unroll
            for (int u = 0; u < 4; u++) {
                float4 svA = *(const float4*)&Ssn[l0 + u][nbase];
                float4 svB = *(const float4*)&Ssn[l0 + u][nbase + 4];
                float sv[8] = {svA.x, svA.y, svA.z, svA.w, svB.x, svB.y, svB.z, svB.w};
#pragma unroll
                for (int nn = 0; nn < 8; nn++) {
                    float d0 = a2[u].x + sv[nn];
                    float d1 = a2[u].y + sv[nn];
                    acc0[nn] += w2[u].x * ex2f(-d0 * d0);
                    acc1[nn] += w2[u].y * ex2f(-d1 * d1);
                }
            }
        }
        __syncthreads();

        int b0r = 2 * lane, b1r = b0r + 1;
#pragma unroll
        for (int g = 0; g < 2; g++) {
            float4 s0 = *(const float4*)&scores[b0r][nbase + g * 4];
            float4 s1 = *(const float4*)&scores[b1r][nbase + g * 4];
            float o0x = rcpf(1.f + ex2f(-LOG2E * (s0.x + acc0[g * 4 + 0])));
            float o0y = rcpf(1.f + ex2f(-LOG2E * (s0.y + acc0[g * 4 + 1])));
            float o0z = rcpf(1.f + ex2f(-LOG2E * (s0.z + acc0[g * 4 + 2])));
            float o0w = rcpf(1.f + ex2f(-LOG2E * (s0.w + acc0[g * 4 + 3])));
            float o1x = rcpf(1.f + ex2f(-LOG2E * (s1.x + acc1[g * 4 + 0])));
            float o1y = rcpf(1.f + ex2f(-LOG2E * (s1.y + acc1[g * 4 + 1])));
            float o1z = rcpf(1.f + ex2f(-LOG2E * (s1.z + acc1[g * 4 + 2])));
            float o1w = rcpf(1.f + ex2f(-LOG2E * (s1.w + acc1[g * 4 + 3])));
            int n = n0 + nbase + g * 4;
            *(float4*)&out[(long)b0r * NE_ + n] = make_float4(o0x, o0y, o0z, o0w);
            *(float4*)&out[(long)b1r * NE_ + n] = make_float4(o1x, o1y, o1z, o1w);
        }
    }
}

// ---------------- launch ----------------
extern "C" void kernel_launch(void* const* d_in, const int* in_sizes, int n_in,
                              void* d_out, int out_size) {
    const int*   e1_idx = (const int*)  d_in[0];
    const int*   r_idx  = (const int*)  d_in[1];
    const float* E      = (const float*)d_in[2];
    const float* R      = (const float*)d_in[3];
    const float* W      = (const float*)d_in[4];
    const float* lits   = (const float*)d_in[5];
    const float* c      = (const float*)d_in[6];
    const float* var_l  = (const float*)d_in[7];
    const float* nf     = (const float*)d_in[8];
    const float* g0     = (const float*)d_in[9];
    const float* b0     = (const float*)d_in[10];
    const float* g1     = (const float*)d_in[11];
    const float* b1     = (const float*)d_in[12];
    float* out = (float*)d_out;

    k_prep<<<28, 256>>>(e1_idx, r_idx, E, R, lits, c, var_l, nf, g0, b0);
    k_wgemm<<<KSPLIT, 256>>>(W);
    k_bn1f<<<13, 512>>>(g1, b1);
    k_score<<<NE_ / 64, 384>>>(E, lits, out);
}